// round 8
// baseline (speedup 1.0000x reference)
#include <cuda_runtime.h>
#include <cuda_bf16.h>
#include <cuda_fp16.h>
#include <cstdint>
#include <type_traits>
#include <math.h>

// Problem constants
#define BATCH 2
#define SEQ   2048
#define DIM   1024
#define HEADS 16
#define HD    64
#define MROWS (BATCH*SEQ)      // 4096
#define QKVN  (3*DIM)          // 3072
#define GK    1024             // K for both GEMMs

// ---------------------------------------------------------------------------
// Scratch (device globals — no allocation allowed)
// ---------------------------------------------------------------------------
__device__ __half        g_qkv[MROWS * QKVN]; // fp16 q|k|v per row
__device__ __nv_bfloat16 g_ah[MROWS * DIM];   // activation hi (x, then ctx)
__device__ __nv_bfloat16 g_al[MROWS * DIM];   // activation lo
__device__ __nv_bfloat16 g_wqh[QKVN * DIM];   // qkv_w^T hi  [N=3072, K=1024]
__device__ __nv_bfloat16 g_wql[QKVN * DIM];   // qkv_w^T lo
__device__ __nv_bfloat16 g_woh[DIM * DIM];    // out_w^T hi  [N=1024, K=1024]
__device__ __nv_bfloat16 g_wol[DIM * DIM];    // out_w^T lo

// ---------------------------------------------------------------------------
// Baseline-PTX helpers (sm_80-era ISA only — compute_100 target rejects tcgen05)
// ---------------------------------------------------------------------------
__device__ __forceinline__ uint32_t smem_to_u32(const void* smem_ptr) {
    uint32_t addr;
    asm("{ .reg .u64 tmp; cvta.to.shared.u64 tmp, %1; cvt.u32.u64 %0, tmp; }"
        : "=r"(addr) : "l"(smem_ptr));
    return addr;
}

#define SWZ(byte_offset) ((byte_offset) ^ (((byte_offset) >> 3) & 0x70))

__device__ __forceinline__ void ldsm_x4(uint32_t& r0, uint32_t& r1,
                                        uint32_t& r2, uint32_t& r3,
                                        uint32_t addr) {
    asm volatile("ldmatrix.sync.aligned.m8n8.x4.shared.b16 {%0,%1,%2,%3}, [%4];"
                 : "=r"(r0), "=r"(r1), "=r"(r2), "=r"(r3) : "r"(addr));
}

__device__ __forceinline__ void ldsm_x4_t(uint32_t& r0, uint32_t& r1,
                                          uint32_t& r2, uint32_t& r3,
                                          uint32_t addr) {
    asm volatile("ldmatrix.sync.aligned.m8n8.x4.trans.shared.b16 {%0,%1,%2,%3}, [%4];"
                 : "=r"(r0), "=r"(r1), "=r"(r2), "=r"(r3) : "r"(addr));
}

// bf16 mma (projection GEMMs)
__device__ __forceinline__ void mma_bf16(float4& c, const uint32_t a[4],
                                         uint32_t b0, uint32_t b1) {
    asm volatile(
        "mma.sync.aligned.m16n8k16.row.col.f32.bf16.bf16.f32 "
        "{%0,%1,%2,%3}, {%4,%5,%6,%7}, {%8,%9}, {%0,%1,%2,%3};"
        : "+f"(c.x), "+f"(c.y), "+f"(c.z), "+f"(c.w)
        : "r"(a[0]), "r"(a[1]), "r"(a[2]), "r"(a[3]), "r"(b0), "r"(b1));
}

// fp16 mma (attention — 4x lower quantization error than bf16, same rate)
__device__ __forceinline__ void mma_fp16(float4& c, const uint32_t a[4],
                                         uint32_t b0, uint32_t b1) {
    asm volatile(
        "mma.sync.aligned.m16n8k16.row.col.f32.f16.f16.f32 "
        "{%0,%1,%2,%3}, {%4,%5,%6,%7}, {%8,%9}, {%0,%1,%2,%3};"
        : "+f"(c.x), "+f"(c.y), "+f"(c.z), "+f"(c.w)
        : "r"(a[0]), "r"(a[1]), "r"(a[2]), "r"(a[3]), "r"(b0), "r"(b1));
}

__device__ __forceinline__ uint32_t pack_half(float a, float b) {
    __half2 t = __floats2half2_rn(a, b);
    return *(uint32_t*)&t;
}

#define CP_ASYNC16(dst, src) \
    asm volatile("cp.async.cg.shared.global [%0], [%1], 16;" \
                 :: "r"(dst), "l"(src))
#define CP_COMMIT() asm volatile("cp.async.commit_group;" ::: "memory")
#define CP_WAIT(n)  asm volatile("cp.async.wait_group %0;" :: "n"(n) : "memory")

// ---------------------------------------------------------------------------
// split kernels: fp32 -> (bf16 hi, bf16 lo)
// ---------------------------------------------------------------------------
struct alignas(8) bf16x4 { __nv_bfloat162 a, b; };

__global__ void split_rows_kernel(const float* __restrict__ in,
                                  __nv_bfloat16* __restrict__ hi,
                                  __nv_bfloat16* __restrict__ lo)
{
    int t = blockIdx.x * blockDim.x + threadIdx.x;
    float4 v = *(const float4*)(in + (size_t)t * 4);
    __nv_bfloat162 h01 = __floats2bfloat162_rn(v.x, v.y);
    __nv_bfloat162 h23 = __floats2bfloat162_rn(v.z, v.w);
    float2 f01 = __bfloat1622float2(h01);
    float2 f23 = __bfloat1622float2(h23);
    __nv_bfloat162 l01 = __floats2bfloat162_rn(v.x - f01.x, v.y - f01.y);
    __nv_bfloat162 l23 = __floats2bfloat162_rn(v.z - f23.x, v.w - f23.y);
    bf16x4 hv; hv.a = h01; hv.b = h23;
    bf16x4 lv; lv.a = l01; lv.b = l23;
    *(bf16x4*)(hi + (size_t)t * 4) = hv;
    *(bf16x4*)(lo + (size_t)t * 4) = lv;
}

// W[K,N] fp32 -> Th/Tl [N,K] bf16 (transpose + split)
__global__ void split_transpose_kernel(const float* __restrict__ W,
                                       __nv_bfloat16* __restrict__ Th,
                                       __nv_bfloat16* __restrict__ Tl,
                                       int K, int N)
{
    __shared__ float t[32][33];
    const int n0 = blockIdx.x * 32, k0 = blockIdx.y * 32;
    const int tx = threadIdx.x, ty = threadIdx.y;  // 32 x 8
    #pragma unroll
    for (int j = 0; j < 32; j += 8)
        t[ty + j][tx] = W[(size_t)(k0 + ty + j) * N + n0 + tx];
    __syncthreads();
    #pragma unroll
    for (int j = 0; j < 32; j += 8) {
        int n = n0 + ty + j;
        float v = t[tx][ty + j];
        __nv_bfloat16 h = __float2bfloat16_rn(v);
        __nv_bfloat16 l = __float2bfloat16_rn(v - __bfloat162float(h));
        Th[(size_t)n * K + k0 + tx] = h;
        Tl[(size_t)n * K + k0 + tx] = l;
    }
}

// ---------------------------------------------------------------------------
// mma.sync split-bf16 GEMM: C[M,N] = (Ah+Al)[M,GK] @ ((Bh+Bl)[N,GK])^T + bias
// 128-thread CTA (4 warps), block tile 128x64, warp tile 64x32, KC=32.
// Per K-chunk, Ah|Al (and Bh|Bl) are packed into the SAME 128B swizzled row:
// bytes [0,64) = hi chunk, [64,128) = lo chunk. 2 CTAs/SM.
// ---------------------------------------------------------------------------
#define KC        32
#define PLA_BYTES (128 * 128)                 // A plane: 128 rows x 128B
#define PLB_BYTES (64 * 128)                  // B plane: 64 rows x 128B
#define BUF_BYTES (PLA_BYTES + PLB_BYTES)     // 24KB
#define GEMM_SMEM (2 * BUF_BYTES + 1024)
#define NCHUNK    (GK / KC)                   // 32

template<typename OutT>
__global__ __launch_bounds__(128, 2)
void gemm_tc_kernel(const __nv_bfloat16* __restrict__ Ah,
                    const __nv_bfloat16* __restrict__ Al,
                    const __nv_bfloat16* __restrict__ Bh,
                    const __nv_bfloat16* __restrict__ Bl,
                    const float* __restrict__ bias,
                    OutT* __restrict__ C, int N)
{
    extern __shared__ char smem_raw[];
    const uint32_t raw  = smem_to_u32(smem_raw);
    const uint32_t base = (raw + 1023u) & ~1023u;

    const int tid  = threadIdx.x;
    const int wid  = tid >> 5;
    const int lane = tid & 31;
    const int wm   = (wid & 1) * 64;
    const int wn   = (wid >> 1) * 32;
    const int m0   = blockIdx.y * 128;
    const int n0   = blockIdx.x * 64;

    auto issue_chunk = [&](int c, int buf) {
        const int k0 = c * KC;
        const uint32_t sb = base + buf * BUF_BYTES;
        // A plane: 1024 16B units (p = 0..7)
        #pragma unroll
        for (int p = 0; p < 8; ++p) {
            int idx = tid + p * 128;
            int r = idx >> 3, u = idx & 7;
            const __nv_bfloat16* src =
                (u < 4 ? Ah : Al) + (size_t)(m0 + r) * GK + k0 + (u & 3) * 8;
            CP_ASYNC16(sb + SWZ((uint32_t)(r * 128 + u * 16)), src);
        }
        // B plane: 512 16B units (p = 0..3)
        #pragma unroll
        for (int p = 0; p < 4; ++p) {
            int idx = tid + p * 128;
            int r = idx >> 3, u = idx & 7;
            const __nv_bfloat16* src =
                (u < 4 ? Bh : Bl) + (size_t)(n0 + r) * GK + k0 + (u & 3) * 8;
            CP_ASYNC16(sb + PLA_BYTES + SWZ((uint32_t)(r * 128 + u * 16)), src);
        }
    };

    float4 acc[4][4];
    #pragma unroll
    for (int i = 0; i < 4; ++i)
        #pragma unroll
        for (int j = 0; j < 4; ++j) acc[i][j] = make_float4(0.f,0.f,0.f,0.f);

    const int a_row = lane & 15;
    const int a_cb  = (lane >> 4) * 16;
    const int b_row = (lane & 7) + ((lane >> 4) & 1) * 8;
    const int b_cb  = ((lane >> 3) & 1) * 16;

    issue_chunk(0, 0);
    CP_COMMIT();

    for (int c = 0; c < NCHUNK; ++c) {
        const int buf = c & 1;
        if (c + 1 < NCHUNK) {
            issue_chunk(c + 1, buf ^ 1);
            CP_COMMIT();
            CP_WAIT(1);
        } else {
            CP_WAIT(0);
        }
        __syncthreads();

        const uint32_t sA = base + buf * BUF_BYTES;
        const uint32_t sB = sA + PLA_BYTES;
        #pragma unroll
        for (int ks = 0; ks < 2; ++ks) {        // 2 x K=16 per 32-chunk
            const int kb = ks * 32;
            uint32_t ah[4][4], al[4][4];
            #pragma unroll
            for (int mi = 0; mi < 4; ++mi) {
                uint32_t roff = (uint32_t)((wm + mi*16 + a_row) * 128);
                ldsm_x4(ah[mi][0], ah[mi][1], ah[mi][2], ah[mi][3],
                        sA + SWZ(roff + kb + a_cb));
                ldsm_x4(al[mi][0], al[mi][1], al[mi][2], al[mi][3],
                        sA + SWZ(roff + 64 + kb + a_cb));
            }
            uint32_t bh[2][4], bl[2][4];
            #pragma unroll
            for (int ni = 0; ni < 2; ++ni) {
                uint32_t roff = (uint32_t)((wn + ni*16 + b_row) * 128);
                ldsm_x4(bh[ni][0], bh[ni][1], bh[ni][2], bh[ni][3],
                        sB + SWZ(roff + kb + b_cb));
                ldsm_x4(bl[ni][0], bl[ni][1], bl[ni][2], bl[ni][3],
                        sB + SWZ(roff + 64 + kb + b_cb));
            }
            #pragma unroll
            for (int mi = 0; mi < 4; ++mi) {
                #pragma unroll
                for (int nj = 0; nj < 4; ++nj) {
                    const int g = nj >> 1, s = (nj & 1) * 2;
                    mma_bf16(acc[mi][nj], ah[mi], bh[g][s], bh[g][s+1]);
                    mma_bf16(acc[mi][nj], ah[mi], bl[g][s], bl[g][s+1]);
                    mma_bf16(acc[mi][nj], al[mi], bh[g][s], bh[g][s+1]);
                }
            }
        }
        __syncthreads();
    }

    const int erow = lane >> 2;
    const int ecol = (lane & 3) * 2;
    #pragma unroll
    for (int mi = 0; mi < 4; ++mi) {
        #pragma unroll
        for (int nj = 0; nj < 4; ++nj) {
            int col = n0 + wn + nj * 8 + ecol;
            float b0 = __ldg(&bias[col]);
            float b1 = __ldg(&bias[col + 1]);
            size_t row = (size_t)(m0 + wm + mi * 16 + erow);
            if constexpr (std::is_same<OutT, float>::value) {
                *(float2*)(C + row * N + col) =
                    make_float2(acc[mi][nj].x + b0, acc[mi][nj].y + b1);
                *(float2*)(C + (row + 8) * N + col) =
                    make_float2(acc[mi][nj].z + b0, acc[mi][nj].w + b1);
            } else {
                *(__half2*)(C + row * N + col) =
                    __floats2half2_rn(acc[mi][nj].x + b0, acc[mi][nj].y + b1);
                *(__half2*)(C + (row + 8) * N + col) =
                    __floats2half2_rn(acc[mi][nj].z + b0, acc[mi][nj].w + b1);
            }
        }
    }
}

// ---------------------------------------------------------------------------
// Tensor-core flash attention (fp16 mma, fp32 accumulate)
// Block: 128 queries of one (b,h); 8 warps x 16 q-rows. 64-key tiles,
// cp.async double-buffered K/V. P fragments stay in registers. V via
// ldmatrix.trans. Scale 1/8 folded into exp. Epilogue writes bf16 hi/lo ctx.
// ---------------------------------------------------------------------------
#define ATT_QB    (128*128)              // Q tile: 16KB
#define ATT_TILEB (64*128)               // K or V tile: 8KB
#define ATT_SMEM  (ATT_QB + 4*ATT_TILEB + 1024 + 64)
#define NKT       (SEQ/64)               // 32 key tiles

__global__ __launch_bounds__(256, 1)
void attn_tc_kernel(const __half* __restrict__ qkv,
                    __nv_bfloat16* __restrict__ ch,
                    __nv_bfloat16* __restrict__ cl)
{
    extern __shared__ char smem_raw[];
    const uint32_t raw  = smem_to_u32(smem_raw);
    const uint32_t base = (raw + 1023u) & ~1023u;
    char* cbase = smem_raw + (base - raw);

    const int tid = threadIdx.x, wid = tid >> 5, lane = tid & 31;
    const int bh = blockIdx.y, b = bh >> 4, h = bh & 15;
    const int q0 = blockIdx.x * 128;

    // Q tile -> smem (SW128 swizzled)
    const __half* qbase = qkv + (size_t)(b*SEQ + q0) * QKVN + h*HD;
    #pragma unroll
    for (int p = 0; p < 4; ++p) {
        int idx = tid + p * 256;
        int r = idx >> 3, u = idx & 7;
        *(uint4*)(cbase + SWZ((uint32_t)(r*128 + u*16))) =
            *(const uint4*)(qbase + (size_t)r * QKVN + u*8);
    }

    const uint32_t sKV0 = base + ATT_QB;
    auto issue_kv = [&](int kt, int buf) {
        const __half* kb_ = qkv + (size_t)(b*SEQ + kt*64) * QKVN + DIM + h*HD;
        const __half* vb_ = kb_ + DIM;
        uint32_t sK = sKV0 + buf * (2*ATT_TILEB);
        #pragma unroll
        for (int p = 0; p < 4; ++p) {
            int idx = tid + p * 256;
            int mat = idx >> 9;            // 0: K, 1: V
            int r   = (idx >> 3) & 63;
            int u   = idx & 7;
            const __half* src = (mat ? vb_ : kb_) + (size_t)r * QKVN + u*8;
            CP_ASYNC16(sK + mat*ATT_TILEB + SWZ((uint32_t)(r*128 + u*16)), src);
        }
    };

    issue_kv(0, 0);
    CP_COMMIT();
    __syncthreads();   // Q visible

    // Q A-fragments, loaded once
    const int ar = lane & 15, acb = (lane >> 4) * 16;
    uint32_t qf[4][4];
    #pragma unroll
    for (int ks = 0; ks < 4; ++ks) {
        uint32_t off = SWZ((uint32_t)((16*wid + ar)*128 + ks*32 + acb));
        ldsm_x4(qf[ks][0], qf[ks][1], qf[ks][2], qf[ks][3], base + off);
    }

    float4 ctx[8];
    #pragma unroll
    for (int nj = 0; nj < 8; ++nj) ctx[nj] = make_float4(0.f,0.f,0.f,0.f);
    float m0 = -1e30f, m1 = -1e30f, l0 = 0.f, l1 = 0.f;

    const int br  = (lane & 7) + ((lane >> 4) & 1) * 8;
    const int bcb = ((lane >> 3) & 1) * 16;

    for (int t = 0; t < NKT; ++t) {
        const int buf = t & 1;
        if (t + 1 < NKT) { issue_kv(t + 1, buf ^ 1); CP_COMMIT(); CP_WAIT(1); }
        else             { CP_WAIT(0); }
        __syncthreads();

        const uint32_t sK = sKV0 + buf * (2*ATT_TILEB);
        const uint32_t sV = sK + ATT_TILEB;

        // scores S[16,64] per warp
        float4 sc[8];
        #pragma unroll
        for (int nj = 0; nj < 8; ++nj) sc[nj] = make_float4(0.f,0.f,0.f,0.f);
        #pragma unroll
        for (int ks = 0; ks < 4; ++ks) {
            uint32_t kf[4][4];
            #pragma unroll
            for (int kg = 0; kg < 4; ++kg) {
                uint32_t off = SWZ((uint32_t)((kg*16 + br)*128 + ks*32 + bcb));
                ldsm_x4(kf[kg][0], kf[kg][1], kf[kg][2], kf[kg][3], sK + off);
            }
            #pragma unroll
            for (int nj = 0; nj < 8; ++nj) {
                const int g = nj >> 1, s = (nj & 1) * 2;
                mma_fp16(sc[nj], qf[ks], kf[g][s], kf[g][s+1]);
            }
        }

        // online softmax (raw-score domain; 1/8 scale inside exp)
        float mx0 = -1e30f, mx1 = -1e30f;
        #pragma unroll
        for (int nj = 0; nj < 8; ++nj) {
            mx0 = fmaxf(mx0, fmaxf(sc[nj].x, sc[nj].y));
            mx1 = fmaxf(mx1, fmaxf(sc[nj].z, sc[nj].w));
        }
        mx0 = fmaxf(mx0, __shfl_xor_sync(0xffffffffu, mx0, 1));
        mx0 = fmaxf(mx0, __shfl_xor_sync(0xffffffffu, mx0, 2));
        mx1 = fmaxf(mx1, __shfl_xor_sync(0xffffffffu, mx1, 1));
        mx1 = fmaxf(mx1, __shfl_xor_sync(0xffffffffu, mx1, 2));
        float nm0 = fmaxf(m0, mx0), nm1 = fmaxf(m1, mx1);
        float f0 = __expf(0.125f * (m0 - nm0));
        float f1 = __expf(0.125f * (m1 - nm1));
        m0 = nm0; m1 = nm1;

        float s0 = 0.f, s1 = 0.f;
        #pragma unroll
        for (int nj = 0; nj < 8; ++nj) {
            sc[nj].x = __expf(0.125f * (sc[nj].x - nm0));
            sc[nj].y = __expf(0.125f * (sc[nj].y - nm0));
            sc[nj].z = __expf(0.125f * (sc[nj].z - nm1));
            sc[nj].w = __expf(0.125f * (sc[nj].w - nm1));
            s0 += sc[nj].x + sc[nj].y;
            s1 += sc[nj].z + sc[nj].w;
        }
        s0 += __shfl_xor_sync(0xffffffffu, s0, 1);
        s0 += __shfl_xor_sync(0xffffffffu, s0, 2);
        s1 += __shfl_xor_sync(0xffffffffu, s1, 1);
        s1 += __shfl_xor_sync(0xffffffffu, s1, 2);
        l0 = l0 * f0 + s0;
        l1 = l1 * f1 + s1;
        #pragma unroll
        for (int nj = 0; nj < 8; ++nj) {
            ctx[nj].x *= f0; ctx[nj].y *= f0;
            ctx[nj].z *= f1; ctx[nj].w *= f1;
        }

        // P A-fragments directly from score C-fragments (fp16)
        uint32_t pf[4][4];
        #pragma unroll
        for (int ks = 0; ks < 4; ++ks) {
            pf[ks][0] = pack_half(sc[2*ks].x,   sc[2*ks].y);
            pf[ks][1] = pack_half(sc[2*ks].z,   sc[2*ks].w);
            pf[ks][2] = pack_half(sc[2*ks+1].x, sc[2*ks+1].y);
            pf[ks][3] = pack_half(sc[2*ks+1].z, sc[2*ks+1].w);
        }

        // ctx += P @ V  (V B-frags via ldmatrix.trans of key-major tile)
        #pragma unroll
        for (int ks = 0; ks < 4; ++ks) {
            uint32_t vf[4][4];
            #pragma unroll
            for (int dp = 0; dp < 4; ++dp) {
                uint32_t off = SWZ((uint32_t)((16*ks + ar)*128 + dp*32 + acb));
                ldsm_x4_t(vf[dp][0], vf[dp][1], vf[dp][2], vf[dp][3], sV + off);
            }
            #pragma unroll
            for (int nj = 0; nj < 8; ++nj) {
                const int g = nj >> 1, s = (nj & 1) * 2;
                mma_fp16(ctx[nj], pf[ks], vf[g][s], vf[g][s+1]);
            }
        }
        __syncthreads();
    }

    // epilogue: normalize, split hi/lo, write to g_ah/g_al (batch offset!)
    const float inv0 = 1.f / l0, inv1 = 1.f / l1;
    const int r0   = b*SEQ + q0 + 16*wid + (lane >> 2);
    const int colb = h*HD + 2*(lane & 3);
    #pragma unroll
    for (int nj = 0; nj < 8; ++nj) {
        int col = colb + 8*nj;
        float v0 = ctx[nj].x * inv0, v1 = ctx[nj].y * inv0;
        float v2 = ctx[nj].z * inv1, v3 = ctx[nj].w * inv1;
        __nv_bfloat162 h01 = __floats2bfloat162_rn(v0, v1);
        __nv_bfloat162 h23 = __floats2bfloat162_rn(v2, v3);
        float2 f01 = __bfloat1622float2(h01);
        float2 f23 = __bfloat1622float2(h23);
        __nv_bfloat162 lo01 = __floats2bfloat162_rn(v0 - f01.x, v1 - f01.y);
        __nv_bfloat162 lo23 = __floats2bfloat162_rn(v2 - f23.x, v3 - f23.y);
        *(__nv_bfloat162*)(ch + (size_t)r0 * DIM + col)       = h01;
        *(__nv_bfloat162*)(cl + (size_t)r0 * DIM + col)       = lo01;
        *(__nv_bfloat162*)(ch + (size_t)(r0+8) * DIM + col)   = h23;
        *(__nv_bfloat162*)(cl + (size_t)(r0+8) * DIM + col)   = lo23;
    }
}

// ---------------------------------------------------------------------------
// Launch
// ---------------------------------------------------------------------------
extern "C" void kernel_launch(void* const* d_in, const int* in_sizes, int n_in,
                              void* d_out, int out_size)
{
    const float* x      = (const float*)d_in[0];
    const float* qkv_w  = (const float*)d_in[2];
    const float* qkv_b  = (const float*)d_in[3];
    const float* out_w  = (const float*)d_in[4];
    const float* out_b  = (const float*)d_in[5];
    float* out = (float*)d_out;

    __half* qkv;
    __nv_bfloat16 *ah, *al, *wqh, *wql, *woh, *wol;
    cudaGetSymbolAddress((void**)&qkv, g_qkv);
    cudaGetSymbolAddress((void**)&ah,  g_ah);
    cudaGetSymbolAddress((void**)&al,  g_al);
    cudaGetSymbolAddress((void**)&wqh, g_wqh);
    cudaGetSymbolAddress((void**)&wql, g_wql);
    cudaGetSymbolAddress((void**)&woh, g_woh);
    cudaGetSymbolAddress((void**)&wol, g_wol);

    cudaFuncSetAttribute(gemm_tc_kernel<__half>,
                         cudaFuncAttributeMaxDynamicSharedMemorySize, GEMM_SMEM);
    cudaFuncSetAttribute(gemm_tc_kernel<float>,
                         cudaFuncAttributeMaxDynamicSharedMemorySize, GEMM_SMEM);
    cudaFuncSetAttribute(attn_tc_kernel,
                         cudaFuncAttributeMaxDynamicSharedMemorySize, ATT_SMEM);

    // 0) split x and weights into bf16 hi/lo
    split_rows_kernel<<<MROWS*DIM/(4*256), 256>>>(x, ah, al);
    split_transpose_kernel<<<dim3(QKVN/32, DIM/32), dim3(32,8)>>>(
        qkv_w, wqh, wql, GK, QKVN);
    split_transpose_kernel<<<dim3(DIM/32, DIM/32), dim3(32,8)>>>(
        out_w, woh, wol, GK, DIM);

    // 1) QKV projection -> fp16 qkv   (block tile 128x64, 128 threads)
    gemm_tc_kernel<__half><<<dim3(QKVN/64, MROWS/128), 128, GEMM_SMEM>>>(
        ah, al, wqh, wql, qkv_b, qkv, QKVN);

    // 2) fp16 tensor-core attention; writes ctx hi/lo splits into ah/al
    attn_tc_kernel<<<dim3(SEQ/128, BATCH*HEADS), 256, ATT_SMEM>>>(qkv, ah, al);

    // 3) output projection (fp32 out)
    gemm_tc_kernel<float><<<dim3(DIM/64, MROWS/128), 128, GEMM_SMEM>>>(
        ah, al, woh, wol, out_b, out, DIM);
}

// round 11
// speedup vs baseline: 1.5177x; 1.5177x over previous
#include <cuda_runtime.h>
#include <cuda_fp16.h>
#include <cstdint>
#include <type_traits>
#include <math.h>

// Problem constants
#define BATCH 2
#define SEQ   2048
#define DIM   1024
#define HEADS 16
#define HD    64
#define MROWS (BATCH*SEQ)      // 4096
#define QKVN  (3*DIM)          // 3072
#define GK    1024             // K for both GEMMs

// ---------------------------------------------------------------------------
// Scratch (device globals — no allocation allowed)
// ---------------------------------------------------------------------------
__device__ __half g_qkv[MROWS * QKVN];   // fp16 q|k|v per row
__device__ __half g_xh [MROWS * DIM];    // x in fp16
__device__ __half g_ctx[MROWS * DIM];    // attention output, fp16
__device__ __half g_wq [QKVN * DIM];     // qkv_w^T fp16  [N=3072, K=1024]
__device__ __half g_wo [DIM * DIM];      // out_w^T fp16  [N=1024, K=1024]

// ---------------------------------------------------------------------------
// Baseline-PTX helpers (sm_80-era ISA only — compute_100 target rejects tcgen05)
// ---------------------------------------------------------------------------
__device__ __forceinline__ uint32_t smem_to_u32(const void* smem_ptr) {
    uint32_t addr;
    asm("{ .reg .u64 tmp; cvta.to.shared.u64 tmp, %1; cvt.u32.u64 %0, tmp; }"
        : "=r"(addr) : "l"(smem_ptr));
    return addr;
}

#define SWZ(byte_offset) ((byte_offset) ^ (((byte_offset) >> 3) & 0x70))

__device__ __forceinline__ void ldsm_x4(uint32_t& r0, uint32_t& r1,
                                        uint32_t& r2, uint32_t& r3,
                                        uint32_t addr) {
    asm volatile("ldmatrix.sync.aligned.m8n8.x4.shared.b16 {%0,%1,%2,%3}, [%4];"
                 : "=r"(r0), "=r"(r1), "=r"(r2), "=r"(r3) : "r"(addr));
}

__device__ __forceinline__ void ldsm_x4_t(uint32_t& r0, uint32_t& r1,
                                          uint32_t& r2, uint32_t& r3,
                                          uint32_t addr) {
    asm volatile("ldmatrix.sync.aligned.m8n8.x4.trans.shared.b16 {%0,%1,%2,%3}, [%4];"
                 : "=r"(r0), "=r"(r1), "=r"(r2), "=r"(r3) : "r"(addr));
}

__device__ __forceinline__ void mma_fp16(float4& c, const uint32_t a[4],
                                         uint32_t b0, uint32_t b1) {
    asm volatile(
        "mma.sync.aligned.m16n8k16.row.col.f32.f16.f16.f32 "
        "{%0,%1,%2,%3}, {%4,%5,%6,%7}, {%8,%9}, {%0,%1,%2,%3};"
        : "+f"(c.x), "+f"(c.y), "+f"(c.z), "+f"(c.w)
        : "r"(a[0]), "r"(a[1]), "r"(a[2]), "r"(a[3]), "r"(b0), "r"(b1));
}

__device__ __forceinline__ uint32_t pack_half(float a, float b) {
    __half2 t = __floats2half2_rn(a, b);
    return *(uint32_t*)&t;
}

#define CP_ASYNC16(dst, src) \
    asm volatile("cp.async.cg.shared.global [%0], [%1], 16;" \
                 :: "r"(dst), "l"(src))
#define CP_COMMIT() asm volatile("cp.async.commit_group;" ::: "memory")
#define CP_WAIT(n)  asm volatile("cp.async.wait_group %0;" :: "n"(n) : "memory")

// ---------------------------------------------------------------------------
// prep kernels: fp32 -> fp16 (rows), fp32 W[K,N] -> fp16 W^T[N,K]
// ---------------------------------------------------------------------------
__global__ void convert_rows_kernel(const float* __restrict__ in,
                                    __half* __restrict__ outp)
{
    int t = blockIdx.x * blockDim.x + threadIdx.x;
    float4 v = *(const float4*)(in + (size_t)t * 4);
    __half2 h01 = __floats2half2_rn(v.x, v.y);
    __half2 h23 = __floats2half2_rn(v.z, v.w);
    uint2 pack = make_uint2(*(uint32_t*)&h01, *(uint32_t*)&h23);
    *(uint2*)(outp + (size_t)t * 4) = pack;
}

__global__ void transpose_h_kernel(const float* __restrict__ W,
                                   __half* __restrict__ T,
                                   int K, int N)
{
    __shared__ float t[32][33];
    const int n0 = blockIdx.x * 32, k0 = blockIdx.y * 32;
    const int tx = threadIdx.x, ty = threadIdx.y;  // 32 x 8
    #pragma unroll
    for (int j = 0; j < 32; j += 8)
        t[ty + j][tx] = W[(size_t)(k0 + ty + j) * N + n0 + tx];
    __syncthreads();
    #pragma unroll
    for (int j = 0; j < 32; j += 8) {
        int n = n0 + ty + j;
        T[(size_t)n * K + k0 + tx] = __float2half_rn(t[tx][ty + j]);
    }
}

// ---------------------------------------------------------------------------
// Single-pass fp16 GEMM: C[M,N] = A[M,GK] @ (B[N,GK])^T + bias
// Block 128x128, 8 warps (warp tile 64x32), KC=64, cp.async double-buffer,
// SW128-swizzled 128B smem rows. fp32 accumulate.
// ---------------------------------------------------------------------------
#define KC        64
#define PLN_BYTES (128 * 128)                 // one plane: 128 rows x 128B
#define BUF_BYTES (2 * PLN_BYTES)             // A | B = 32KB
#define GEMM_SMEM (2 * BUF_BYTES + 1024)
#define NCHUNK    (GK / KC)                   // 16

template<typename OutT>
__global__ __launch_bounds__(256, 1)
void gemm_h_kernel(const __half* __restrict__ A,
                   const __half* __restrict__ B,
                   const float* __restrict__ bias,
                   OutT* __restrict__ C, int N)
{
    extern __shared__ char smem_raw[];
    const uint32_t raw  = smem_to_u32(smem_raw);
    const uint32_t base = (raw + 1023u) & ~1023u;

    const int tid  = threadIdx.x;
    const int wid  = tid >> 5;
    const int lane = tid & 31;
    const int wm   = (wid & 1) * 64;
    const int wn   = (wid >> 1) * 32;
    const int m0   = blockIdx.y * 128;
    const int n0   = blockIdx.x * 128;

    auto issue_chunk = [&](int c, int buf) {
        const int k0 = c * KC;
        const uint32_t sb = base + buf * BUF_BYTES;
        #pragma unroll
        for (int p = 0; p < 4; ++p) {        // A plane: 1024 16B units
            int idx = tid + p * 256;
            int r = idx >> 3, u = idx & 7;
            CP_ASYNC16(sb + SWZ((uint32_t)(r * 128 + u * 16)),
                       A + (size_t)(m0 + r) * GK + k0 + u * 8);
        }
        #pragma unroll
        for (int p = 0; p < 4; ++p) {        // B plane
            int idx = tid + p * 256;
            int r = idx >> 3, u = idx & 7;
            CP_ASYNC16(sb + PLN_BYTES + SWZ((uint32_t)(r * 128 + u * 16)),
                       B + (size_t)(n0 + r) * GK + k0 + u * 8);
        }
    };

    float4 acc[4][4];
    #pragma unroll
    for (int i = 0; i < 4; ++i)
        #pragma unroll
        for (int j = 0; j < 4; ++j) acc[i][j] = make_float4(0.f,0.f,0.f,0.f);

    const int a_row = lane & 15;
    const int a_cb  = (lane >> 4) * 16;
    const int b_row = (lane & 7) + ((lane >> 4) & 1) * 8;
    const int b_cb  = ((lane >> 3) & 1) * 16;

    issue_chunk(0, 0);
    CP_COMMIT();

    for (int c = 0; c < NCHUNK; ++c) {
        const int buf = c & 1;
        if (c + 1 < NCHUNK) {
            issue_chunk(c + 1, buf ^ 1);
            CP_COMMIT();
            CP_WAIT(1);
        } else {
            CP_WAIT(0);
        }
        __syncthreads();

        const uint32_t sA = base + buf * BUF_BYTES;
        const uint32_t sB = sA + PLN_BYTES;
        #pragma unroll
        for (int ks = 0; ks < 4; ++ks) {       // 4 x K=16 per 64-chunk
            const int kb = ks * 32;
            uint32_t af[4][4];
            #pragma unroll
            for (int mi = 0; mi < 4; ++mi) {
                uint32_t off = SWZ((uint32_t)((wm + mi*16 + a_row) * 128 + kb + a_cb));
                ldsm_x4(af[mi][0], af[mi][1], af[mi][2], af[mi][3], sA + off);
            }
            uint32_t bf[2][4];
            #pragma unroll
            for (int ni = 0; ni < 2; ++ni) {
                uint32_t off = SWZ((uint32_t)((wn + ni*16 + b_row) * 128 + kb + b_cb));
                ldsm_x4(bf[ni][0], bf[ni][1], bf[ni][2], bf[ni][3], sB + off);
            }
            #pragma unroll
            for (int mi = 0; mi < 4; ++mi) {
                #pragma unroll
                for (int nj = 0; nj < 4; ++nj) {
                    const int g = nj >> 1, s = (nj & 1) * 2;
                    mma_fp16(acc[mi][nj], af[mi], bf[g][s], bf[g][s+1]);
                }
            }
        }
        __syncthreads();
    }

    const int erow = lane >> 2;
    const int ecol = (lane & 3) * 2;
    #pragma unroll
    for (int mi = 0; mi < 4; ++mi) {
        #pragma unroll
        for (int nj = 0; nj < 4; ++nj) {
            int col = n0 + wn + nj * 8 + ecol;
            float b0 = __ldg(&bias[col]);
            float b1 = __ldg(&bias[col + 1]);
            size_t row = (size_t)(m0 + wm + mi * 16 + erow);
            if constexpr (std::is_same<OutT, float>::value) {
                *(float2*)(C + row * N + col) =
                    make_float2(acc[mi][nj].x + b0, acc[mi][nj].y + b1);
                *(float2*)(C + (row + 8) * N + col) =
                    make_float2(acc[mi][nj].z + b0, acc[mi][nj].w + b1);
            } else {
                *(__half2*)(C + row * N + col) =
                    __floats2half2_rn(acc[mi][nj].x + b0, acc[mi][nj].y + b1);
                *(__half2*)(C + (row + 8) * N + col) =
                    __floats2half2_rn(acc[mi][nj].z + b0, acc[mi][nj].w + b1);
            }
        }
    }
}

// ---------------------------------------------------------------------------
// Tensor-core flash attention (fp16 mma, fp32 accumulate) — unchanged core.
// Epilogue writes single fp16 ctx.
// ---------------------------------------------------------------------------
#define ATT_QB    (128*128)              // Q tile: 16KB
#define ATT_TILEB (64*128)               // K or V tile: 8KB
#define ATT_SMEM  (ATT_QB + 4*ATT_TILEB + 1024 + 64)
#define NKT       (SEQ/64)               // 32 key tiles

__global__ __launch_bounds__(256, 1)
void attn_tc_kernel(const __half* __restrict__ qkv,
                    __half* __restrict__ ctxo)
{
    extern __shared__ char smem_raw[];
    const uint32_t raw  = smem_to_u32(smem_raw);
    const uint32_t base = (raw + 1023u) & ~1023u;
    char* cbase = smem_raw + (base - raw);

    const int tid = threadIdx.x, wid = tid >> 5, lane = tid & 31;
    const int bh = blockIdx.y, b = bh >> 4, h = bh & 15;
    const int q0 = blockIdx.x * 128;

    // Q tile -> smem (SW128 swizzled)
    const __half* qbase = qkv + (size_t)(b*SEQ + q0) * QKVN + h*HD;
    #pragma unroll
    for (int p = 0; p < 4; ++p) {
        int idx = tid + p * 256;
        int r = idx >> 3, u = idx & 7;
        *(uint4*)(cbase + SWZ((uint32_t)(r*128 + u*16))) =
            *(const uint4*)(qbase + (size_t)r * QKVN + u*8);
    }

    const uint32_t sKV0 = base + ATT_QB;
    auto issue_kv = [&](int kt, int buf) {
        const __half* kb_ = qkv + (size_t)(b*SEQ + kt*64) * QKVN + DIM + h*HD;
        const __half* vb_ = kb_ + DIM;
        uint32_t sK = sKV0 + buf * (2*ATT_TILEB);
        #pragma unroll
        for (int p = 0; p < 4; ++p) {
            int idx = tid + p * 256;
            int mat = idx >> 9;            // 0: K, 1: V
            int r   = (idx >> 3) & 63;
            int u   = idx & 7;
            const __half* src = (mat ? vb_ : kb_) + (size_t)r * QKVN + u*8;
            CP_ASYNC16(sK + mat*ATT_TILEB + SWZ((uint32_t)(r*128 + u*16)), src);
        }
    };

    issue_kv(0, 0);
    CP_COMMIT();
    __syncthreads();   // Q visible

    // Q A-fragments, loaded once
    const int ar = lane & 15, acb = (lane >> 4) * 16;
    uint32_t qf[4][4];
    #pragma unroll
    for (int ks = 0; ks < 4; ++ks) {
        uint32_t off = SWZ((uint32_t)((16*wid + ar)*128 + ks*32 + acb));
        ldsm_x4(qf[ks][0], qf[ks][1], qf[ks][2], qf[ks][3], base + off);
    }

    float4 ctx[8];
    #pragma unroll
    for (int nj = 0; nj < 8; ++nj) ctx[nj] = make_float4(0.f,0.f,0.f,0.f);
    float m0 = -1e30f, m1 = -1e30f, l0 = 0.f, l1 = 0.f;

    const int br  = (lane & 7) + ((lane >> 4) & 1) * 8;
    const int bcb = ((lane >> 3) & 1) * 16;

    for (int t = 0; t < NKT; ++t) {
        const int buf = t & 1;
        if (t + 1 < NKT) { issue_kv(t + 1, buf ^ 1); CP_COMMIT(); CP_WAIT(1); }
        else             { CP_WAIT(0); }
        __syncthreads();

        const uint32_t sK = sKV0 + buf * (2*ATT_TILEB);
        const uint32_t sV = sK + ATT_TILEB;

        // scores S[16,64] per warp
        float4 sc[8];
        #pragma unroll
        for (int nj = 0; nj < 8; ++nj) sc[nj] = make_float4(0.f,0.f,0.f,0.f);
        #pragma unroll
        for (int ks = 0; ks < 4; ++ks) {
            uint32_t kf[4][4];
            #pragma unroll
            for (int kg = 0; kg < 4; ++kg) {
                uint32_t off = SWZ((uint32_t)((kg*16 + br)*128 + ks*32 + bcb));
                ldsm_x4(kf[kg][0], kf[kg][1], kf[kg][2], kf[kg][3], sK + off);
            }
            #pragma unroll
            for (int nj = 0; nj < 8; ++nj) {
                const int g = nj >> 1, s = (nj & 1) * 2;
                mma_fp16(sc[nj], qf[ks], kf[g][s], kf[g][s+1]);
            }
        }

        // online softmax (raw-score domain; 1/8 scale inside exp)
        float mx0 = -1e30f, mx1 = -1e30f;
        #pragma unroll
        for (int nj = 0; nj < 8; ++nj) {
            mx0 = fmaxf(mx0, fmaxf(sc[nj].x, sc[nj].y));
            mx1 = fmaxf(mx1, fmaxf(sc[nj].z, sc[nj].w));
        }
        mx0 = fmaxf(mx0, __shfl_xor_sync(0xffffffffu, mx0, 1));
        mx0 = fmaxf(mx0, __shfl_xor_sync(0xffffffffu, mx0, 2));
        mx1 = fmaxf(mx1, __shfl_xor_sync(0xffffffffu, mx1, 1));
        mx1 = fmaxf(mx1, __shfl_xor_sync(0xffffffffu, mx1, 2));
        float nm0 = fmaxf(m0, mx0), nm1 = fmaxf(m1, mx1);
        float f0 = __expf(0.125f * (m0 - nm0));
        float f1 = __expf(0.125f * (m1 - nm1));
        m0 = nm0; m1 = nm1;

        float s0 = 0.f, s1 = 0.f;
        #pragma unroll
        for (int nj = 0; nj < 8; ++nj) {
            sc[nj].x = __expf(0.125f * (sc[nj].x - nm0));
            sc[nj].y = __expf(0.125f * (sc[nj].y - nm0));
            sc[nj].z = __expf(0.125f * (sc[nj].z - nm1));
            sc[nj].w = __expf(0.125f * (sc[nj].w - nm1));
            s0 += sc[nj].x + sc[nj].y;
            s1 += sc[nj].z + sc[nj].w;
        }
        s0 += __shfl_xor_sync(0xffffffffu, s0, 1);
        s0 += __shfl_xor_sync(0xffffffffu, s0, 2);
        s1 += __shfl_xor_sync(0xffffffffu, s1, 1);
        s1 += __shfl_xor_sync(0xffffffffu, s1, 2);
        l0 = l0 * f0 + s0;
        l1 = l1 * f1 + s1;
        #pragma unroll
        for (int nj = 0; nj < 8; ++nj) {
            ctx[nj].x *= f0; ctx[nj].y *= f0;
            ctx[nj].z *= f1; ctx[nj].w *= f1;
        }

        // P A-fragments directly from score C-fragments (fp16)
        uint32_t pf[4][4];
        #pragma unroll
        for (int ks = 0; ks < 4; ++ks) {
            pf[ks][0] = pack_half(sc[2*ks].x,   sc[2*ks].y);
            pf[ks][1] = pack_half(sc[2*ks].z,   sc[2*ks].w);
            pf[ks][2] = pack_half(sc[2*ks+1].x, sc[2*ks+1].y);
            pf[ks][3] = pack_half(sc[2*ks+1].z, sc[2*ks+1].w);
        }

        // ctx += P @ V  (V B-frags via ldmatrix.trans of key-major tile)
        #pragma unroll
        for (int ks = 0; ks < 4; ++ks) {
            uint32_t vf[4][4];
            #pragma unroll
            for (int dp = 0; dp < 4; ++dp) {
                uint32_t off = SWZ((uint32_t)((16*ks + ar)*128 + dp*32 + acb));
                ldsm_x4_t(vf[dp][0], vf[dp][1], vf[dp][2], vf[dp][3], sV + off);
            }
            #pragma unroll
            for (int nj = 0; nj < 8; ++nj) {
                const int g = nj >> 1, s = (nj & 1) * 2;
                mma_fp16(ctx[nj], pf[ks], vf[g][s], vf[g][s+1]);
            }
        }
        __syncthreads();
    }

    // epilogue: normalize, write fp16 ctx (batch offset included)
    const float inv0 = 1.f / l0, inv1 = 1.f / l1;
    const int r0   = b*SEQ + q0 + 16*wid + (lane >> 2);
    const int colb = h*HD + 2*(lane & 3);
    #pragma unroll
    for (int nj = 0; nj < 8; ++nj) {
        int col = colb + 8*nj;
        *(__half2*)(ctxo + (size_t)r0 * DIM + col) =
            __floats2half2_rn(ctx[nj].x * inv0, ctx[nj].y * inv0);
        *(__half2*)(ctxo + (size_t)(r0+8) * DIM + col) =
            __floats2half2_rn(ctx[nj].z * inv1, ctx[nj].w * inv1);
    }
}

// ---------------------------------------------------------------------------
// Launch
// ---------------------------------------------------------------------------
extern "C" void kernel_launch(void* const* d_in, const int* in_sizes, int n_in,
                              void* d_out, int out_size)
{
    const float* x      = (const float*)d_in[0];
    const float* qkv_w  = (const float*)d_in[2];
    const float* qkv_b  = (const float*)d_in[3];
    const float* out_w  = (const float*)d_in[4];
    const float* out_b  = (const float*)d_in[5];
    float* out = (float*)d_out;

    __half *qkv, *xh, *ctx, *wq, *wo;
    cudaGetSymbolAddress((void**)&qkv, g_qkv);
    cudaGetSymbolAddress((void**)&xh,  g_xh);
    cudaGetSymbolAddress((void**)&ctx, g_ctx);
    cudaGetSymbolAddress((void**)&wq,  g_wq);
    cudaGetSymbolAddress((void**)&wo,  g_wo);

    cudaFuncSetAttribute(gemm_h_kernel<__half>,
                         cudaFuncAttributeMaxDynamicSharedMemorySize, GEMM_SMEM);
    cudaFuncSetAttribute(gemm_h_kernel<float>,
                         cudaFuncAttributeMaxDynamicSharedMemorySize, GEMM_SMEM);
    cudaFuncSetAttribute(attn_tc_kernel,
                         cudaFuncAttributeMaxDynamicSharedMemorySize, ATT_SMEM);

    // 0) convert x -> fp16, transpose weights -> fp16
    convert_rows_kernel<<<MROWS*DIM/(4*256), 256>>>(x, xh);
    transpose_h_kernel<<<dim3(QKVN/32, DIM/32), dim3(32,8)>>>(qkv_w, wq, GK, QKVN);
    transpose_h_kernel<<<dim3(DIM/32, DIM/32), dim3(32,8)>>>(out_w, wo, GK, DIM);

    // 1) QKV projection (single-pass fp16) -> fp16 qkv
    gemm_h_kernel<__half><<<dim3(QKVN/128, MROWS/128), 256, GEMM_SMEM>>>(
        xh, wq, qkv_b, qkv, QKVN);

    // 2) fp16 tensor-core attention -> fp16 ctx
    attn_tc_kernel<<<dim3(SEQ/128, BATCH*HEADS), 256, ATT_SMEM>>>(qkv, ctx);

    // 3) output projection (single-pass fp16, fp32 out)
    gemm_h_kernel<float><<<dim3(DIM/128, MROWS/128), 256, GEMM_SMEM>>>(
        ctx, wo, out_b, out, DIM);
}

// round 12
// speedup vs baseline: 1.6487x; 1.0863x over previous
#include <cuda_runtime.h>
#include <cuda_fp16.h>
#include <cstdint>
#include <type_traits>
#include <math.h>

// Problem constants
#define BATCH 2
#define SEQ   2048
#define DIM   1024
#define HEADS 16
#define HD    64
#define MROWS (BATCH*SEQ)      // 4096
#define QKVN  (3*DIM)          // 3072
#define GK    1024             // K for both GEMMs

// ---------------------------------------------------------------------------
// Scratch (device globals — no allocation allowed)
// ---------------------------------------------------------------------------
__device__ __half g_qkv[MROWS * QKVN];   // fp16 q|k|v per row
__device__ __half g_xh [MROWS * DIM];    // x in fp16
__device__ __half g_ctx[MROWS * DIM];    // attention output, fp16
__device__ __half g_wq [QKVN * DIM];     // qkv_w^T fp16  [N=3072, K=1024]
__device__ __half g_wo [DIM * DIM];      // out_w^T fp16  [N=1024, K=1024]

// ---------------------------------------------------------------------------
// Baseline-PTX helpers (sm_80-era ISA only — compute_100 target rejects tcgen05)
// ---------------------------------------------------------------------------
__device__ __forceinline__ uint32_t smem_to_u32(const void* smem_ptr) {
    uint32_t addr;
    asm("{ .reg .u64 tmp; cvta.to.shared.u64 tmp, %1; cvt.u32.u64 %0, tmp; }"
        : "=r"(addr) : "l"(smem_ptr));
    return addr;
}

#define SWZ(byte_offset) ((byte_offset) ^ (((byte_offset) >> 3) & 0x70))

__device__ __forceinline__ void ldsm_x4(uint32_t& r0, uint32_t& r1,
                                        uint32_t& r2, uint32_t& r3,
                                        uint32_t addr) {
    asm volatile("ldmatrix.sync.aligned.m8n8.x4.shared.b16 {%0,%1,%2,%3}, [%4];"
                 : "=r"(r0), "=r"(r1), "=r"(r2), "=r"(r3) : "r"(addr));
}

__device__ __forceinline__ void ldsm_x4_t(uint32_t& r0, uint32_t& r1,
                                          uint32_t& r2, uint32_t& r3,
                                          uint32_t addr) {
    asm volatile("ldmatrix.sync.aligned.m8n8.x4.trans.shared.b16 {%0,%1,%2,%3}, [%4];"
                 : "=r"(r0), "=r"(r1), "=r"(r2), "=r"(r3) : "r"(addr));
}

__device__ __forceinline__ void mma_fp16(float4& c, const uint32_t a[4],
                                         uint32_t b0, uint32_t b1) {
    asm volatile(
        "mma.sync.aligned.m16n8k16.row.col.f32.f16.f16.f32 "
        "{%0,%1,%2,%3}, {%4,%5,%6,%7}, {%8,%9}, {%0,%1,%2,%3};"
        : "+f"(c.x), "+f"(c.y), "+f"(c.z), "+f"(c.w)
        : "r"(a[0]), "r"(a[1]), "r"(a[2]), "r"(a[3]), "r"(b0), "r"(b1));
}

__device__ __forceinline__ uint32_t pack_half(float a, float b) {
    __half2 t = __floats2half2_rn(a, b);
    return *(uint32_t*)&t;
}

#define CP_ASYNC16(dst, src) \
    asm volatile("cp.async.cg.shared.global [%0], [%1], 16;" \
                 :: "r"(dst), "l"(src))
#define CP_COMMIT() asm volatile("cp.async.commit_group;" ::: "memory")
#define CP_WAIT(n)  asm volatile("cp.async.wait_group %0;" :: "n"(n) : "memory")

// ---------------------------------------------------------------------------
// prep kernels: fp32 -> fp16 (rows), fp32 W[K,N] -> fp16 W^T[N,K]
// ---------------------------------------------------------------------------
__global__ void convert_rows_kernel(const float* __restrict__ in,
                                    __half* __restrict__ outp)
{
    int t = blockIdx.x * blockDim.x + threadIdx.x;
    float4 v = *(const float4*)(in + (size_t)t * 4);
    __half2 h01 = __floats2half2_rn(v.x, v.y);
    __half2 h23 = __floats2half2_rn(v.z, v.w);
    uint2 pack = make_uint2(*(uint32_t*)&h01, *(uint32_t*)&h23);
    *(uint2*)(outp + (size_t)t * 4) = pack;
}

__global__ void transpose_h_kernel(const float* __restrict__ W,
                                   __half* __restrict__ T,
                                   int K, int N)
{
    __shared__ float t[32][33];
    const int n0 = blockIdx.x * 32, k0 = blockIdx.y * 32;
    const int tx = threadIdx.x, ty = threadIdx.y;  // 32 x 8
    #pragma unroll
    for (int j = 0; j < 32; j += 8)
        t[ty + j][tx] = W[(size_t)(k0 + ty + j) * N + n0 + tx];
    __syncthreads();
    #pragma unroll
    for (int j = 0; j < 32; j += 8) {
        int n = n0 + ty + j;
        T[(size_t)n * K + k0 + tx] = __float2half_rn(t[tx][ty + j]);
    }
}

// ---------------------------------------------------------------------------
// Single-pass fp16 GEMM: C[M,N] = A[M,GK] @ (B[N,GK])^T + bias
// 128-thread CTA (4 warps), block tile 128x64, warp tile 64x32, KC=64,
// cp.async double-buffer, SW128 swizzle, fp32 accumulate. 4 CTAs/SM.
// ---------------------------------------------------------------------------
#define KC        64
#define PLA_BYTES (128 * 128)                 // A plane: 128 rows x 128B
#define PLB_BYTES (64 * 128)                  // B plane: 64 rows x 128B
#define BUF_BYTES (PLA_BYTES + PLB_BYTES)     // 24KB
#define GEMM_SMEM (2 * BUF_BYTES + 1024)
#define NCHUNK    (GK / KC)                   // 16

template<typename OutT>
__global__ __launch_bounds__(128, 4)
void gemm_h_kernel(const __half* __restrict__ A,
                   const __half* __restrict__ B,
                   const float* __restrict__ bias,
                   OutT* __restrict__ C, int N)
{
    extern __shared__ char smem_raw[];
    const uint32_t raw  = smem_to_u32(smem_raw);
    const uint32_t base = (raw + 1023u) & ~1023u;

    const int tid  = threadIdx.x;
    const int wid  = tid >> 5;
    const int lane = tid & 31;
    const int wm   = (wid & 1) * 64;    // warp m-offset
    const int wn   = (wid >> 1) * 32;   // warp n-offset
    const int m0   = blockIdx.y * 128;
    const int n0   = blockIdx.x * 64;

    auto issue_chunk = [&](int c, int buf) {
        const int k0 = c * KC;
        const uint32_t sb = base + buf * BUF_BYTES;
        #pragma unroll
        for (int p = 0; p < 8; ++p) {        // A plane: 1024 16B units
            int idx = tid + p * 128;
            int r = idx >> 3, u = idx & 7;
            CP_ASYNC16(sb + SWZ((uint32_t)(r * 128 + u * 16)),
                       A + (size_t)(m0 + r) * GK + k0 + u * 8);
        }
        #pragma unroll
        for (int p = 0; p < 4; ++p) {        // B plane: 512 16B units
            int idx = tid + p * 128;
            int r = idx >> 3, u = idx & 7;
            CP_ASYNC16(sb + PLA_BYTES + SWZ((uint32_t)(r * 128 + u * 16)),
                       B + (size_t)(n0 + r) * GK + k0 + u * 8);
        }
    };

    float4 acc[4][4];
    #pragma unroll
    for (int i = 0; i < 4; ++i)
        #pragma unroll
        for (int j = 0; j < 4; ++j) acc[i][j] = make_float4(0.f,0.f,0.f,0.f);

    const int a_row = lane & 15;
    const int a_cb  = (lane >> 4) * 16;
    const int b_row = (lane & 7) + ((lane >> 4) & 1) * 8;
    const int b_cb  = ((lane >> 3) & 1) * 16;

    issue_chunk(0, 0);
    CP_COMMIT();

    for (int c = 0; c < NCHUNK; ++c) {
        const int buf = c & 1;
        if (c + 1 < NCHUNK) {
            issue_chunk(c + 1, buf ^ 1);
            CP_COMMIT();
            CP_WAIT(1);
        } else {
            CP_WAIT(0);
        }
        __syncthreads();

        const uint32_t sA = base + buf * BUF_BYTES;
        const uint32_t sB = sA + PLA_BYTES;
        #pragma unroll
        for (int ks = 0; ks < 4; ++ks) {       // 4 x K=16 per 64-chunk
            const int kb = ks * 32;
            uint32_t af[4][4];
            #pragma unroll
            for (int mi = 0; mi < 4; ++mi) {
                uint32_t off = SWZ((uint32_t)((wm + mi*16 + a_row) * 128 + kb + a_cb));
                ldsm_x4(af[mi][0], af[mi][1], af[mi][2], af[mi][3], sA + off);
            }
            uint32_t bf[2][4];
            #pragma unroll
            for (int ni = 0; ni < 2; ++ni) {
                uint32_t off = SWZ((uint32_t)((wn + ni*16 + b_row) * 128 + kb + b_cb));
                ldsm_x4(bf[ni][0], bf[ni][1], bf[ni][2], bf[ni][3], sB + off);
            }
            #pragma unroll
            for (int mi = 0; mi < 4; ++mi) {
                #pragma unroll
                for (int nj = 0; nj < 4; ++nj) {
                    const int g = nj >> 1, s = (nj & 1) * 2;
                    mma_fp16(acc[mi][nj], af[mi], bf[g][s], bf[g][s+1]);
                }
            }
        }
        __syncthreads();
    }

    const int erow = lane >> 2;
    const int ecol = (lane & 3) * 2;
    #pragma unroll
    for (int mi = 0; mi < 4; ++mi) {
        #pragma unroll
        for (int nj = 0; nj < 4; ++nj) {
            int col = n0 + wn + nj * 8 + ecol;
            float b0 = __ldg(&bias[col]);
            float b1 = __ldg(&bias[col + 1]);
            size_t row = (size_t)(m0 + wm + mi * 16 + erow);
            if constexpr (std::is_same<OutT, float>::value) {
                *(float2*)(C + row * N + col) =
                    make_float2(acc[mi][nj].x + b0, acc[mi][nj].y + b1);
                *(float2*)(C + (row + 8) * N + col) =
                    make_float2(acc[mi][nj].z + b0, acc[mi][nj].w + b1);
            } else {
                *(__half2*)(C + row * N + col) =
                    __floats2half2_rn(acc[mi][nj].x + b0, acc[mi][nj].y + b1);
                *(__half2*)(C + (row + 8) * N + col) =
                    __floats2half2_rn(acc[mi][nj].z + b0, acc[mi][nj].w + b1);
            }
        }
    }
}

// ---------------------------------------------------------------------------
// Tensor-core flash attention (fp16 mma, fp32 accumulate) — unchanged.
// ---------------------------------------------------------------------------
#define ATT_QB    (128*128)              // Q tile: 16KB
#define ATT_TILEB (64*128)               // K or V tile: 8KB
#define ATT_SMEM  (ATT_QB + 4*ATT_TILEB + 1024 + 64)
#define NKT       (SEQ/64)               // 32 key tiles

__global__ __launch_bounds__(256, 1)
void attn_tc_kernel(const __half* __restrict__ qkv,
                    __half* __restrict__ ctxo)
{
    extern __shared__ char smem_raw[];
    const uint32_t raw  = smem_to_u32(smem_raw);
    const uint32_t base = (raw + 1023u) & ~1023u;
    char* cbase = smem_raw + (base - raw);

    const int tid = threadIdx.x, wid = tid >> 5, lane = tid & 31;
    const int bh = blockIdx.y, b = bh >> 4, h = bh & 15;
    const int q0 = blockIdx.x * 128;

    // Q tile -> smem (SW128 swizzled)
    const __half* qbase = qkv + (size_t)(b*SEQ + q0) * QKVN + h*HD;
    #pragma unroll
    for (int p = 0; p < 4; ++p) {
        int idx = tid + p * 256;
        int r = idx >> 3, u = idx & 7;
        *(uint4*)(cbase + SWZ((uint32_t)(r*128 + u*16))) =
            *(const uint4*)(qbase + (size_t)r * QKVN + u*8);
    }

    const uint32_t sKV0 = base + ATT_QB;
    auto issue_kv = [&](int kt, int buf) {
        const __half* kb_ = qkv + (size_t)(b*SEQ + kt*64) * QKVN + DIM + h*HD;
        const __half* vb_ = kb_ + DIM;
        uint32_t sK = sKV0 + buf * (2*ATT_TILEB);
        #pragma unroll
        for (int p = 0; p < 4; ++p) {
            int idx = tid + p * 256;
            int mat = idx >> 9;            // 0: K, 1: V
            int r   = (idx >> 3) & 63;
            int u   = idx & 7;
            const __half* src = (mat ? vb_ : kb_) + (size_t)r * QKVN + u*8;
            CP_ASYNC16(sK + mat*ATT_TILEB + SWZ((uint32_t)(r*128 + u*16)), src);
        }
    };

    issue_kv(0, 0);
    CP_COMMIT();
    __syncthreads();   // Q visible

    // Q A-fragments, loaded once
    const int ar = lane & 15, acb = (lane >> 4) * 16;
    uint32_t qf[4][4];
    #pragma unroll
    for (int ks = 0; ks < 4; ++ks) {
        uint32_t off = SWZ((uint32_t)((16*wid + ar)*128 + ks*32 + acb));
        ldsm_x4(qf[ks][0], qf[ks][1], qf[ks][2], qf[ks][3], base + off);
    }

    float4 ctx[8];
    #pragma unroll
    for (int nj = 0; nj < 8; ++nj) ctx[nj] = make_float4(0.f,0.f,0.f,0.f);
    float m0 = -1e30f, m1 = -1e30f, l0 = 0.f, l1 = 0.f;

    const int br  = (lane & 7) + ((lane >> 4) & 1) * 8;
    const int bcb = ((lane >> 3) & 1) * 16;

    for (int t = 0; t < NKT; ++t) {
        const int buf = t & 1;
        if (t + 1 < NKT) { issue_kv(t + 1, buf ^ 1); CP_COMMIT(); CP_WAIT(1); }
        else             { CP_WAIT(0); }
        __syncthreads();

        const uint32_t sK = sKV0 + buf * (2*ATT_TILEB);
        const uint32_t sV = sK + ATT_TILEB;

        // scores S[16,64] per warp
        float4 sc[8];
        #pragma unroll
        for (int nj = 0; nj < 8; ++nj) sc[nj] = make_float4(0.f,0.f,0.f,0.f);
        #pragma unroll
        for (int ks = 0; ks < 4; ++ks) {
            uint32_t kf[4][4];
            #pragma unroll
            for (int kg = 0; kg < 4; ++kg) {
                uint32_t off = SWZ((uint32_t)((kg*16 + br)*128 + ks*32 + bcb));
                ldsm_x4(kf[kg][0], kf[kg][1], kf[kg][2], kf[kg][3], sK + off);
            }
            #pragma unroll
            for (int nj = 0; nj < 8; ++nj) {
                const int g = nj >> 1, s = (nj & 1) * 2;
                mma_fp16(sc[nj], qf[ks], kf[g][s], kf[g][s+1]);
            }
        }

        // online softmax (raw-score domain; 1/8 scale inside exp)
        float mx0 = -1e30f, mx1 = -1e30f;
        #pragma unroll
        for (int nj = 0; nj < 8; ++nj) {
            mx0 = fmaxf(mx0, fmaxf(sc[nj].x, sc[nj].y));
            mx1 = fmaxf(mx1, fmaxf(sc[nj].z, sc[nj].w));
        }
        mx0 = fmaxf(mx0, __shfl_xor_sync(0xffffffffu, mx0, 1));
        mx0 = fmaxf(mx0, __shfl_xor_sync(0xffffffffu, mx0, 2));
        mx1 = fmaxf(mx1, __shfl_xor_sync(0xffffffffu, mx1, 1));
        mx1 = fmaxf(mx1, __shfl_xor_sync(0xffffffffu, mx1, 2));
        float nm0 = fmaxf(m0, mx0), nm1 = fmaxf(m1, mx1);
        float f0 = __expf(0.125f * (m0 - nm0));
        float f1 = __expf(0.125f * (m1 - nm1));
        m0 = nm0; m1 = nm1;

        float s0 = 0.f, s1 = 0.f;
        #pragma unroll
        for (int nj = 0; nj < 8; ++nj) {
            sc[nj].x = __expf(0.125f * (sc[nj].x - nm0));
            sc[nj].y = __expf(0.125f * (sc[nj].y - nm0));
            sc[nj].z = __expf(0.125f * (sc[nj].z - nm1));
            sc[nj].w = __expf(0.125f * (sc[nj].w - nm1));
            s0 += sc[nj].x + sc[nj].y;
            s1 += sc[nj].z + sc[nj].w;
        }
        s0 += __shfl_xor_sync(0xffffffffu, s0, 1);
        s0 += __shfl_xor_sync(0xffffffffu, s0, 2);
        s1 += __shfl_xor_sync(0xffffffffu, s1, 1);
        s1 += __shfl_xor_sync(0xffffffffu, s1, 2);
        l0 = l0 * f0 + s0;
        l1 = l1 * f1 + s1;
        #pragma unroll
        for (int nj = 0; nj < 8; ++nj) {
            ctx[nj].x *= f0; ctx[nj].y *= f0;
            ctx[nj].z *= f1; ctx[nj].w *= f1;
        }

        // P A-fragments directly from score C-fragments (fp16)
        uint32_t pf[4][4];
        #pragma unroll
        for (int ks = 0; ks < 4; ++ks) {
            pf[ks][0] = pack_half(sc[2*ks].x,   sc[2*ks].y);
            pf[ks][1] = pack_half(sc[2*ks].z,   sc[2*ks].w);
            pf[ks][2] = pack_half(sc[2*ks+1].x, sc[2*ks+1].y);
            pf[ks][3] = pack_half(sc[2*ks+1].z, sc[2*ks+1].w);
        }

        // ctx += P @ V  (V B-frags via ldmatrix.trans of key-major tile)
        #pragma unroll
        for (int ks = 0; ks < 4; ++ks) {
            uint32_t vf[4][4];
            #pragma unroll
            for (int dp = 0; dp < 4; ++dp) {
                uint32_t off = SWZ((uint32_t)((16*ks + ar)*128 + dp*32 + acb));
                ldsm_x4_t(vf[dp][0], vf[dp][1], vf[dp][2], vf[dp][3], sV + off);
            }
            #pragma unroll
            for (int nj = 0; nj < 8; ++nj) {
                const int g = nj >> 1, s = (nj & 1) * 2;
                mma_fp16(ctx[nj], pf[ks], vf[g][s], vf[g][s+1]);
            }
        }
        __syncthreads();
    }

    // epilogue: normalize, write fp16 ctx (batch offset included)
    const float inv0 = 1.f / l0, inv1 = 1.f / l1;
    const int r0   = b*SEQ + q0 + 16*wid + (lane >> 2);
    const int colb = h*HD + 2*(lane & 3);
    #pragma unroll
    for (int nj = 0; nj < 8; ++nj) {
        int col = colb + 8*nj;
        *(__half2*)(ctxo + (size_t)r0 * DIM + col) =
            __floats2half2_rn(ctx[nj].x * inv0, ctx[nj].y * inv0);
        *(__half2*)(ctxo + (size_t)(r0+8) * DIM + col) =
            __floats2half2_rn(ctx[nj].z * inv1, ctx[nj].w * inv1);
    }
}

// ---------------------------------------------------------------------------
// Launch
// ---------------------------------------------------------------------------
extern "C" void kernel_launch(void* const* d_in, const int* in_sizes, int n_in,
                              void* d_out, int out_size)
{
    const float* x      = (const float*)d_in[0];
    const float* qkv_w  = (const float*)d_in[2];
    const float* qkv_b  = (const float*)d_in[3];
    const float* out_w  = (const float*)d_in[4];
    const float* out_b  = (const float*)d_in[5];
    float* out = (float*)d_out;

    __half *qkv, *xh, *ctx, *wq, *wo;
    cudaGetSymbolAddress((void**)&qkv, g_qkv);
    cudaGetSymbolAddress((void**)&xh,  g_xh);
    cudaGetSymbolAddress((void**)&ctx, g_ctx);
    cudaGetSymbolAddress((void**)&wq,  g_wq);
    cudaGetSymbolAddress((void**)&wo,  g_wo);

    cudaFuncSetAttribute(gemm_h_kernel<__half>,
                         cudaFuncAttributeMaxDynamicSharedMemorySize, GEMM_SMEM);
    cudaFuncSetAttribute(gemm_h_kernel<float>,
                         cudaFuncAttributeMaxDynamicSharedMemorySize, GEMM_SMEM);
    cudaFuncSetAttribute(attn_tc_kernel,
                         cudaFuncAttributeMaxDynamicSharedMemorySize, ATT_SMEM);

    // 0) convert x -> fp16, transpose weights -> fp16
    convert_rows_kernel<<<MROWS*DIM/(4*256), 256>>>(x, xh);
    transpose_h_kernel<<<dim3(QKVN/32, DIM/32), dim3(32,8)>>>(qkv_w, wq, GK, QKVN);
    transpose_h_kernel<<<dim3(DIM/32, DIM/32), dim3(32,8)>>>(out_w, wo, GK, DIM);

    // 1) QKV projection (single-pass fp16, 128x64 tiles) -> fp16 qkv
    gemm_h_kernel<__half><<<dim3(QKVN/64, MROWS/128), 128, GEMM_SMEM>>>(
        xh, wq, qkv_b, qkv, QKVN);

    // 2) fp16 tensor-core attention -> fp16 ctx
    attn_tc_kernel<<<dim3(SEQ/128, BATCH*HEADS), 256, ATT_SMEM>>>(qkv, ctx);

    // 3) output projection (single-pass fp16, fp32 out)
    gemm_h_kernel<float><<<dim3(DIM/64, MROWS/128), 128, GEMM_SMEM>>>(
        ctx, wo, out_b, out, DIM);
}